// round 16
// baseline (speedup 1.0000x reference)
#include <cuda_runtime.h>
#include <cuda_fp16.h>
#include <cstdint>
#include <cstddef>

#define DIM     512
#define BATCH   8
#define SEQ     4096
#define M_TOTAL (BATCH * SEQ)   // 32768

// ---------------------------------------------------------------------------
// Scratch (__device__ globals; no allocation allowed)
// ---------------------------------------------------------------------------
__device__ __half  g_xh[(size_t)M_TOTAL * DIM];   // x fp16
__device__ __half  g_qh[(size_t)M_TOTAL * DIM];   // q -> qn (fp16, in place)
__device__ __half  g_kh[(size_t)M_TOTAL * DIM];   // k -> kn (fp16, in place)
__device__ __half  g_wT[3u * DIM * DIM];          // wq^T, wk^T, wf^T fp16
__device__ __half  g_wps[(size_t)BATCH * DIM * DIM]; // diag(gq_b)*wp, row-major [k][j]
__device__ __half  g_w1T[(size_t)BATCH * DIM * DIM]; // (Bp@wf)^T per batch: [n][k]
__device__ float   g_gq[BATCH * DIM];
__device__ float   g_b2[DIM];                     // bp@wf + bf

// ---------------------------------------------------------------------------
// helpers
// ---------------------------------------------------------------------------
__device__ __forceinline__ uint32_t smem_u32(const void* p) {
    uint32_t a;
    asm("{ .reg .u64 t; cvta.to.shared.u64 t, %1; cvt.u32.u64 %0, t; }" : "=r"(a) : "l"(p));
    return a;
}
__device__ __forceinline__ uint32_t swz(uint32_t o) { return o ^ ((o >> 3) & 0x70); }

__device__ __forceinline__ void cp16(uint32_t s, const void* g) {
    asm volatile("cp.async.cg.shared.global [%0], [%1], 16;\n" :: "r"(s), "l"(g));
}
#define CP_COMMIT() asm volatile("cp.async.commit_group;\n" ::: "memory")
#define CP_WAIT1()  asm volatile("cp.async.wait_group 1;\n" ::: "memory")

__device__ __forceinline__ void ldsm4(uint32_t* r, uint32_t addr) {
    asm volatile("ldmatrix.sync.aligned.m8n8.x4.shared.b16 {%0,%1,%2,%3}, [%4];\n"
                 : "=r"(r[0]), "=r"(r[1]), "=r"(r[2]), "=r"(r[3]) : "r"(addr));
}
__device__ __forceinline__ void mma16816(float* d, const uint32_t* a, const uint32_t* b) {
    asm volatile(
        "mma.sync.aligned.m16n8k16.row.col.f32.f16.f16.f32 "
        "{%0,%1,%2,%3}, {%4,%5,%6,%7}, {%8,%9}, {%0,%1,%2,%3};\n"
        : "+f"(d[0]), "+f"(d[1]), "+f"(d[2]), "+f"(d[3])
        : "r"(a[0]), "r"(a[1]), "r"(a[2]), "r"(a[3]), "r"(b[0]), "r"(b[1]));
}

// ---------------------------------------------------------------------------
// fp16 GEMM, CTA 128x128, 256 thr, 3-stage cp.async, occ 2.
// MODE 0: GEMM1. B0 has 1024 rows. cols <512 -> out0h/bias0, >=512 -> out1h/bias1.
// MODE 3: fused GEMM23. 16 chunks: c<8 (A0=kn, B0=w1T per batch), c>=8 (A1=qn,
//         B1=wfT). fp32 out + fp32 bias0 (bias2).
// MODE 4: W1 build. A0 = wfT with rows replicated mod 512; B0 = wps per
//         512-row group; fp16 out0h, no bias.
// ---------------------------------------------------------------------------
#define STAGES 3
#define GEMM_SMEM (STAGES * 32768)   // 96 KB

__device__ __forceinline__ void load_chunk(
    const __half* __restrict__ A, const __half* __restrict__ B,
    int m0, int n0, int k0, uint32_t sA, uint32_t sB, int t)
{
    const int ch = t & 7;          // 16B chunk within 128B row
    const int rb = t >> 3;         // 0..31
#pragma unroll
    for (int it = 0; it < 4; it++) {
        int r = it * 32 + rb;
        cp16(sA + swz((uint32_t)(r * 128 + ch * 16)),
             A + (size_t)(m0 + r) * DIM + k0 + ch * 8);
    }
#pragma unroll
    for (int it = 0; it < 4; it++) {
        int r = it * 32 + rb;
        cp16(sB + swz((uint32_t)(r * 128 + ch * 16)),
             B + (size_t)(n0 + r) * DIM + k0 + ch * 8);
    }
}

template <int MODE>
__global__ __launch_bounds__(256, 2)
void mma_gemm(const __half* __restrict__ A0, const __half* __restrict__ A1,
              const __half* __restrict__ B0, const __half* __restrict__ B1,
              const float* __restrict__ bias0, const float* __restrict__ bias1,
              float* __restrict__ outF,
              __half* __restrict__ out0h, __half* __restrict__ out1h)
{
    constexpr int NCH = (MODE == 3) ? 16 : 8;
    extern __shared__ char smem[];
    const uint32_t sb = smem_u32(smem);
    const int t = threadIdx.x;
    const int w = t >> 5, l = t & 31;
    const int m0 = blockIdx.y * 128;
    const int n0 = blockIdx.x * 128;

    if (MODE == 3) B0 += (size_t)(m0 / SEQ) * DIM * DIM;
    if (MODE == 4) B0 += (size_t)(m0 / 512) * DIM * DIM;
    const int am0 = (MODE == 4) ? (m0 & 511) : m0;

    uint32_t sA[STAGES], sB[STAGES];
#pragma unroll
    for (int s = 0; s < STAGES; s++) { sA[s] = sb + s * 32768u; sB[s] = sA[s] + 16384u; }

    load_chunk(A0, B0, am0, n0, 0,  sA[0], sB[0], t); CP_COMMIT();
    load_chunk(A0, B0, am0, n0, 64, sA[1], sB[1], t); CP_COMMIT();

    const int wm = w & 1;          // M half (0/1) -> 64 rows
    const int wn = w >> 1;         // N quarter (0..3) -> 32 cols
    const uint32_t aBase = (uint32_t)((wm * 64 + (l & 15)) * 128 + (l >> 4) * 16);
    const uint32_t bBase = (uint32_t)((wn * 32 + ((l >> 4) * 8) + (l & 7)) * 128
                                      + ((l >> 3) & 1) * 16);

    float acc[4][4][4];
#pragma unroll
    for (int i = 0; i < 4; i++)
#pragma unroll
        for (int j = 0; j < 4; j++)
#pragma unroll
            for (int e = 0; e < 4; e++) acc[i][j][e] = 0.0f;

    for (int c = 0; c < NCH; c++) {
        CP_WAIT1();
        __syncthreads();
        const int pf = c + 2;
        if (pf < NCH) {
            const __half* Ap = (MODE == 3 && pf >= 8) ? A1 : A0;
            const __half* Bp = (MODE == 3 && pf >= 8) ? B1 : B0;
            load_chunk(Ap, Bp, am0, n0, (pf & 7) * 64, sA[pf % 3], sB[pf % 3], t);
        }
        CP_COMMIT();

        const uint32_t cA = sA[c % 3], cB = sB[c % 3];
#pragma unroll
        for (int s = 0; s < 4; s++) {
            uint32_t a[4][4], b[4][2];
#pragma unroll
            for (int i = 0; i < 4; i++) {
                uint32_t off = aBase + i * 2048 + s * 32;
                ldsm4(a[i], cA + (off ^ ((off >> 3) & 0x70)));
            }
#pragma unroll
            for (int jj = 0; jj < 2; jj++) {
                uint32_t off = bBase + jj * 2048 + s * 32;
                uint32_t r[4];
                ldsm4(r, cB + (off ^ ((off >> 3) & 0x70)));
                b[2 * jj][0] = r[0]; b[2 * jj][1] = r[1];
                b[2 * jj + 1][0] = r[2]; b[2 * jj + 1][1] = r[3];
            }
#pragma unroll
            for (int i = 0; i < 4; i++)
#pragma unroll
                for (int j = 0; j < 4; j++)
                    mma16816(acc[i][j], a[i], b[j]);
        }
    }

    // ---- epilogue ----
    const float* bias = bias0;
    __half* outh = out0h;
    int cb = n0;
    if (MODE == 0 && n0 >= 512) { bias = bias1; outh = out1h; cb = n0 - 512; }

    const int colw = cb + wn * 32 + (l & 3) * 2;
    float bj[4][2];
#pragma unroll
    for (int j = 0; j < 4; j++) {
        if (MODE == 4) { bj[j][0] = 0.f; bj[j][1] = 0.f; }
        else { bj[j][0] = bias[colw + j * 8]; bj[j][1] = bias[colw + j * 8 + 1]; }
    }

    const int mrow = m0 + wm * 64 + (l >> 2);
#pragma unroll
    for (int i = 0; i < 4; i++) {
        int r0 = mrow + i * 16, r1 = r0 + 8;
#pragma unroll
        for (int j = 0; j < 4; j++) {
            int cc = colw + j * 8;
            float v0 = acc[i][j][0] + bj[j][0];
            float v1 = acc[i][j][1] + bj[j][1];
            float v2 = acc[i][j][2] + bj[j][0];
            float v3 = acc[i][j][3] + bj[j][1];
            size_t o0 = (size_t)r0 * DIM + cc;
            size_t o1 = (size_t)r1 * DIM + cc;
            if (MODE == 3) {
                *reinterpret_cast<float2*>(outF + o0) = make_float2(v0, v1);
                *reinterpret_cast<float2*>(outF + o1) = make_float2(v2, v3);
            } else {
                *reinterpret_cast<__half2*>(outh + o0) = __floats2half2_rn(v0, v1);
                *reinterpret_cast<__half2*>(outh + o1) = __floats2half2_rn(v2, v3);
            }
        }
    }
}

// ---------------------------------------------------------------------------
// x -> fp16 (partial grid; base = float4 offset)
// ---------------------------------------------------------------------------
__global__ void cvt_x_kernel(const float* __restrict__ x, __half* __restrict__ h,
                             size_t base)
{
    size_t i = base + (size_t)blockIdx.x * blockDim.x + threadIdx.x;
    float4 v = reinterpret_cast<const float4*>(x)[i];
    reinterpret_cast<__half2*>(h)[2 * i]     = __floats2half2_rn(v.x, v.y);
    reinterpret_cast<__half2*>(h)[2 * i + 1] = __floats2half2_rn(v.z, v.w);
}

// ---------------------------------------------------------------------------
// Transpose + convert one weight: th[zoff*D*D + n*D + k] = fp16(w[k][n])
// ---------------------------------------------------------------------------
__global__ void wsplit_kernel(const float* __restrict__ w,
                              __half* __restrict__ th, int zoff)
{
    __shared__ float sm[32][33];
    const int n0 = blockIdx.x * 32, k0 = blockIdx.y * 32;
    sm[threadIdx.y][threadIdx.x] = w[(size_t)(k0 + threadIdx.y) * DIM + n0 + threadIdx.x];
    __syncthreads();
    float v = sm[threadIdx.x][threadIdx.y];
    size_t o = (size_t)zoff * DIM * DIM + (size_t)(n0 + threadIdx.y) * DIM + k0 + threadIdx.x;
    th[o] = __float2half_rn(v);
}

// wps[b][k][j] = fp16(gq[b][k] * wp[k][j])   (no transpose)
__global__ void wpscale_kernel(const float* __restrict__ wp,
                               const float* __restrict__ gq,
                               __half* __restrict__ th)
{
    const int b = blockIdx.y;
    const int i = (blockIdx.x * 256 + threadIdx.x) * 2;
    const int k = i >> 9;
    const float g = gq[b * DIM + k];
    float2 v = *reinterpret_cast<const float2*>(wp + i);
    *reinterpret_cast<__half2*>(th + (size_t)b * DIM * DIM + i) =
        __floats2half2_rn(v.x * g, v.y * g);
}

// bias2[n] = sum_k bp[k]*wf[k][n] + bf[n]
__global__ void bias2_kernel(const float* __restrict__ wf,
                             const float* __restrict__ bp,
                             const float* __restrict__ bf,
                             float* __restrict__ b2)
{
    const int n = blockIdx.x * 128 + threadIdx.x;
    float s = bf[n];
#pragma unroll 8
    for (int k = 0; k < DIM; k++)
        s += bp[k] * wf[(size_t)k * DIM + n];
    b2[n] = s;
}

// ---------------------------------------------------------------------------
// L2-normalize q and k (fp16 in place), warp-per-row. Proven round-11 form.
// ---------------------------------------------------------------------------
__device__ __forceinline__ float ss_acc(uint4 v) {
    const __half2* h = reinterpret_cast<const __half2*>(&v);
    float s = 0.f;
#pragma unroll
    for (int i = 0; i < 4; i++) {
        float2 f = __half22float2(h[i]);
        s += f.x * f.x + f.y * f.y;
    }
    return s;
}
__device__ __forceinline__ uint4 scale4(uint4 v, float r) {
    __half2* h = reinterpret_cast<__half2*>(&v);
#pragma unroll
    for (int i = 0; i < 4; i++) {
        float2 f = __half22float2(h[i]);
        h[i] = __floats2half2_rn(f.x * r, f.y * r);
    }
    return v;
}

__global__ void l2norm_kernel(__half* __restrict__ q, __half* __restrict__ k)
{
    const int lane = threadIdx.x & 31;
    const int wid  = threadIdx.x >> 5;
    const int row  = blockIdx.x * 8 + wid;

    uint4* qp = reinterpret_cast<uint4*>(q + (size_t)row * DIM);
    uint4* kp = reinterpret_cast<uint4*>(k + (size_t)row * DIM);
    uint4 q0 = qp[2 * lane], q1 = qp[2 * lane + 1];
    uint4 k0 = kp[2 * lane], k1 = kp[2 * lane + 1];

    float sq = ss_acc(q0) + ss_acc(q1);
    float sk = ss_acc(k0) + ss_acc(k1);
#pragma unroll
    for (int o = 16; o > 0; o >>= 1) {
        sq += __shfl_xor_sync(0xFFFFFFFFu, sq, o);
        sk += __shfl_xor_sync(0xFFFFFFFFu, sk, o);
    }
    const float rq = rsqrtf(fmaxf(sq, 1e-12f));
    const float rk = rsqrtf(fmaxf(sk, 1e-12f));

    qp[2 * lane]     = scale4(q0, rq);
    qp[2 * lane + 1] = scale4(q1, rq);
    kp[2 * lane]     = scale4(k0, rk);
    kp[2 * lane + 1] = scale4(k1, rk);
}

__global__ void zero_gq_kernel(float* __restrict__ gq)
{
    int i = blockIdx.x * blockDim.x + threadIdx.x;
    if (i < BATCH * DIM) gq[i] = 0.0f;
}

// gq[b,d] = sum_n qn[b,n,d]  (qn normalized fp16)
__global__ void batch_sum_kernel(const __half* __restrict__ qn, float* __restrict__ gq)
{
    const int d4 = threadIdx.x;
    const int b  = blockIdx.y;
    const int n0 = blockIdx.z * 256;
    const __half2* base = reinterpret_cast<const __half2*>(
        qn + ((size_t)b * SEQ + n0) * DIM) + 2 * d4;
    float s0 = 0.f, s1 = 0.f, s2 = 0.f, s3 = 0.f;
#pragma unroll 8
    for (int i = 0; i < 256; i++) {
        float2 v0 = __half22float2(base[(size_t)i * (DIM / 2)]);
        float2 v1 = __half22float2(base[(size_t)i * (DIM / 2) + 1]);
        s0 += v0.x; s1 += v0.y; s2 += v1.x; s3 += v1.y;
    }
    float* g = gq + b * DIM + d4 * 4;
    atomicAdd(g + 0, s0);
    atomicAdd(g + 1, s1);
    atomicAdd(g + 2, s2);
    atomicAdd(g + 3, s3);
}

// ---------------------------------------------------------------------------
extern "C" void kernel_launch(void* const* d_in, const int* in_sizes, int n_in,
                              void* d_out, int out_size)
{
    const float* x  = (const float*)d_in[0];
    const float* wq = (const float*)d_in[1];
    const float* bq = (const float*)d_in[2];
    const float* wk = (const float*)d_in[3];
    const float* bk = (const float*)d_in[4];
    const float* wp = (const float*)d_in[5];
    const float* bp = (const float*)d_in[6];
    const float* wf = (const float*)d_in[7];
    const float* bf = (const float*)d_in[8];
    // d_in[9] = w_g: softmax over size-1 axis == 1 -> unused
    float* out = (float*)d_out;

    __half *xh, *qh, *kh, *wT, *wps, *w1T;
    float *gq, *b2;
    cudaGetSymbolAddress((void**)&xh,  g_xh);
    cudaGetSymbolAddress((void**)&qh,  g_qh);
    cudaGetSymbolAddress((void**)&kh,  g_kh);
    cudaGetSymbolAddress((void**)&wT,  g_wT);
    cudaGetSymbolAddress((void**)&wps, g_wps);
    cudaGetSymbolAddress((void**)&w1T, g_w1T);
    cudaGetSymbolAddress((void**)&gq,  g_gq);
    cudaGetSymbolAddress((void**)&b2,  g_b2);

    cudaFuncSetAttribute(mma_gemm<0>, cudaFuncAttributeMaxDynamicSharedMemorySize, GEMM_SMEM);
    cudaFuncSetAttribute(mma_gemm<3>, cudaFuncAttributeMaxDynamicSharedMemorySize, GEMM_SMEM);
    cudaFuncSetAttribute(mma_gemm<4>, cudaFuncAttributeMaxDynamicSharedMemorySize, GEMM_SMEM);

    const int MT = M_TOTAL / 128;            // 256 row tiles
    const size_t NV4 = (size_t)M_TOTAL * DIM / 4;

    // launches 0-4 (prep; GEMM1 is launch index 5 for ncu -s 5 -c 1)
    cvt_x_kernel<<<NV4 / 2 / 256, 256>>>(x, xh, 0);
    cvt_x_kernel<<<NV4 / 2 / 256, 256>>>(x, xh, NV4 / 2);
    wsplit_kernel<<<dim3(16, 16), dim3(32, 32)>>>(wq, wT, 0);
    wsplit_kernel<<<dim3(16, 16), dim3(32, 32)>>>(wk, wT, 1);
    wsplit_kernel<<<dim3(16, 16), dim3(32, 32)>>>(wf, wT, 2);

    // launch 5: fused q,k GEMM (B rows 0..511 wq^T, 512..1023 wk^T)
    mma_gemm<0><<<dim3(8, MT), 256, GEMM_SMEM>>>(xh, nullptr, wT, nullptr,
                                                 bq, bk, nullptr, qh, kh);
    // normalize (fp16 in place, warp per row)
    l2norm_kernel<<<M_TOTAL / 8, 256>>>(qh, kh);
    zero_gq_kernel<<<(BATCH * DIM + 255) / 256, 256>>>(gq);
    // gq = per-batch sum of qn
    batch_sum_kernel<<<dim3(1, BATCH, SEQ / 256), 128>>>(qh, gq);
    // Bp = diag(gq_b)*wp  (row-major, fp16)
    wpscale_kernel<<<dim3(DIM * DIM / 512, BATCH), 256>>>(wp, gq, wps);
    // bias2 = bp@wf + bf
    bias2_kernel<<<4, 128>>>(wf, bp, bf, b2);
    // W1^T[b] = wf^T @ Bp^T : M=4096 (rows replicated mod 512), per-512 B
    mma_gemm<4><<<dim3(4, 32), 256, GEMM_SMEM>>>(wT + 2u * DIM * DIM, nullptr,
                                                 wps, nullptr,
                                                 nullptr, nullptr, nullptr,
                                                 w1T, nullptr);
    // out = kn@W1 + qn@wf + bias2   (fused GEMM2+3, K'=1024)
    mma_gemm<3><<<dim3(4, MT), 256, GEMM_SMEM>>>(kh, qh, w1T, wT + 2u * DIM * DIM,
                                                 b2, nullptr, out, nullptr, nullptr);
}

// round 17
// speedup vs baseline: 1.0218x; 1.0218x over previous
#include <cuda_runtime.h>
#include <cuda_fp16.h>
#include <cstdint>
#include <cstddef>

#define DIM     512
#define BATCH   8
#define SEQ     4096
#define M_TOTAL (BATCH * SEQ)   // 32768

// ---------------------------------------------------------------------------
// Scratch (__device__ globals; no allocation allowed)
// ---------------------------------------------------------------------------
__device__ __half  g_uh[(size_t)M_TOTAL * DIM];   // u fp16 (GEMM2 out)
__device__ __half  g_qh[(size_t)M_TOTAL * DIM];   // q -> qn (fp16, in place)
__device__ __half  g_kh[(size_t)M_TOTAL * DIM];   // k -> kn (fp16, in place)
__device__ __half  g_wT[3u * DIM * DIM];          // wq^T, wk^T, wf^T fp16 (concat rows)
__device__ __half  g_wpT[(size_t)BATCH * DIM * DIM]; // (diag(gq_b) wp)^T fp16
__device__ float   g_gq[BATCH * DIM];

// ---------------------------------------------------------------------------
// helpers
// ---------------------------------------------------------------------------
__device__ __forceinline__ uint32_t smem_u32(const void* p) {
    uint32_t a;
    asm("{ .reg .u64 t; cvta.to.shared.u64 t, %1; cvt.u32.u64 %0, t; }" : "=r"(a) : "l"(p));
    return a;
}
__device__ __forceinline__ uint32_t swz(uint32_t o) { return o ^ ((o >> 3) & 0x70); }

__device__ __forceinline__ uint32_t h2_bits(__half2 v) {
    uint32_t u;
    *reinterpret_cast<__half2*>(&u) = v;
    return u;
}

__device__ __forceinline__ void cp16(uint32_t s, const void* g) {
    asm volatile("cp.async.cg.shared.global [%0], [%1], 16;\n" :: "r"(s), "l"(g));
}
#define CP_COMMIT() asm volatile("cp.async.commit_group;\n" ::: "memory")
#define CP_WAIT1()  asm volatile("cp.async.wait_group 1;\n" ::: "memory")

__device__ __forceinline__ void ldsm4(uint32_t* r, uint32_t addr) {
    asm volatile("ldmatrix.sync.aligned.m8n8.x4.shared.b16 {%0,%1,%2,%3}, [%4];\n"
                 : "=r"(r[0]), "=r"(r[1]), "=r"(r[2]), "=r"(r[3]) : "r"(addr));
}
__device__ __forceinline__ void mma16816(float* d, const uint32_t* a, const uint32_t* b) {
    asm volatile(
        "mma.sync.aligned.m16n8k16.row.col.f32.f16.f16.f32 "
        "{%0,%1,%2,%3}, {%4,%5,%6,%7}, {%8,%9}, {%0,%1,%2,%3};\n"
        : "+f"(d[0]), "+f"(d[1]), "+f"(d[2]), "+f"(d[3])
        : "r"(a[0]), "r"(a[1]), "r"(a[2]), "r"(a[3]), "r"(b[0]), "r"(b[1]));
}

#define STAGES 3
#define GEMM_SMEM (STAGES * 32768)   // 96 KB

// ===========================================================================
// GEMM1: [q | k] = x(fp32, converted in-kernel) @ [wq^T | wk^T]^T + [bq | bk]
// CTA 128x128, 256 thr, occ 2, 3-stage. A: LDG fp32 -> cvt -> STS (immediate,
// no values held across barriers). B: cp.async fp16.
// ===========================================================================
__device__ __forceinline__ void g1_loadB(const __half* __restrict__ B,
                                         int n0, int k0, uint32_t sB, int t)
{
    const int ch = t & 7;
    const int rb = t >> 3;         // 0..31
#pragma unroll
    for (int it = 0; it < 4; it++) {
        int r = it * 32 + rb;
        cp16(sB + swz((uint32_t)(r * 128 + ch * 16)),
             B + (size_t)(n0 + r) * DIM + k0 + ch * 8);
    }
}

__device__ __forceinline__ void g1_cvtA(const float* __restrict__ x,
                                        int m0, int k0, uint32_t sA, int t)
{
    const int g  = t & 7;          // 8-float group in 64-wide row
    const int rb = t >> 3;         // 0..31
#pragma unroll
    for (int it = 0; it < 4; it++) {
        int r = it * 32 + rb;
        const float* p = x + (size_t)(m0 + r) * DIM + k0 + g * 8;
        float4 f0 = *reinterpret_cast<const float4*>(p);
        float4 f1 = *reinterpret_cast<const float4*>(p + 4);
        uint32_t h0 = h2_bits(__floats2half2_rn(f0.x, f0.y));
        uint32_t h1 = h2_bits(__floats2half2_rn(f0.z, f0.w));
        uint32_t h2 = h2_bits(__floats2half2_rn(f1.x, f1.y));
        uint32_t h3 = h2_bits(__floats2half2_rn(f1.z, f1.w));
        uint32_t so = sA + swz((uint32_t)(r * 128 + g * 16));
        asm volatile("st.shared.v4.b32 [%0], {%1,%2,%3,%4};\n"
                     :: "r"(so), "r"(h0), "r"(h1), "r"(h2), "r"(h3));
    }
}

__global__ __launch_bounds__(256, 2)
void mma_gemm1(const float* __restrict__ x, const __half* __restrict__ B,
               const float* __restrict__ bq, const float* __restrict__ bk,
               __half* __restrict__ qh, __half* __restrict__ kh)
{
    extern __shared__ char smem[];
    const uint32_t sb = smem_u32(smem);
    const int t = threadIdx.x;
    const int w = t >> 5, l = t & 31;
    const int m0 = blockIdx.y * 128;
    const int n0 = blockIdx.x * 128;

    uint32_t sA[STAGES], sB[STAGES];
#pragma unroll
    for (int s = 0; s < STAGES; s++) { sA[s] = sb + s * 32768u; sB[s] = sA[s] + 16384u; }

    // prologue
    g1_loadB(B, n0, 0,  sB[0], t); CP_COMMIT();
    g1_loadB(B, n0, 64, sB[1], t); CP_COMMIT();
    g1_cvtA(x, m0, 0,  sA[0], t);
    g1_cvtA(x, m0, 64, sA[1], t);

    const int wm = w & 1;
    const int wn = w >> 1;
    const uint32_t aBase = (uint32_t)((wm * 64 + (l & 15)) * 128 + (l >> 4) * 16);
    const uint32_t bBase = (uint32_t)((wn * 32 + ((l >> 4) * 8) + (l & 7)) * 128
                                      + ((l >> 3) & 1) * 16);

    float acc[4][4][4];
#pragma unroll
    for (int i = 0; i < 4; i++)
#pragma unroll
        for (int j = 0; j < 4; j++)
#pragma unroll
            for (int e = 0; e < 4; e++) acc[i][j][e] = 0.0f;

    for (int c = 0; c < 8; c++) {
        CP_WAIT1();
        __syncthreads();
        const int pf = c + 2;
        if (pf < 8) g1_loadB(B, n0, pf * 64, sB[pf % 3], t);
        CP_COMMIT();
        if (pf < 8) g1_cvtA(x, m0, pf * 64, sA[pf % 3], t);

        const uint32_t cA = sA[c % 3], cB = sB[c % 3];
#pragma unroll
        for (int s = 0; s < 4; s++) {
            uint32_t a[4][4], b[4][2];
#pragma unroll
            for (int i = 0; i < 4; i++) {
                uint32_t off = aBase + i * 2048 + s * 32;
                ldsm4(a[i], cA + (off ^ ((off >> 3) & 0x70)));
            }
#pragma unroll
            for (int jj = 0; jj < 2; jj++) {
                uint32_t off = bBase + jj * 2048 + s * 32;
                uint32_t r[4];
                ldsm4(r, cB + (off ^ ((off >> 3) & 0x70)));
                b[2 * jj][0] = r[0]; b[2 * jj][1] = r[1];
                b[2 * jj + 1][0] = r[2]; b[2 * jj + 1][1] = r[3];
            }
#pragma unroll
            for (int i = 0; i < 4; i++)
#pragma unroll
                for (int j = 0; j < 4; j++)
                    mma16816(acc[i][j], a[i], b[j]);
        }
    }

    // epilogue: n0 < 512 -> q/bq ; else k/bk
    const float* bias = (n0 < 512) ? bq : bk;
    __half* outh      = (n0 < 512) ? qh : kh;
    const int cb = n0 & 511;

    const int colw = cb + wn * 32 + (l & 3) * 2;
    float bj[4][2];
#pragma unroll
    for (int j = 0; j < 4; j++) {
        bj[j][0] = bias[colw + j * 8];
        bj[j][1] = bias[colw + j * 8 + 1];
    }

    const int mrow = m0 + wm * 64 + (l >> 2);
#pragma unroll
    for (int i = 0; i < 4; i++) {
        int r0 = mrow + i * 16, r1 = r0 + 8;
#pragma unroll
        for (int j = 0; j < 4; j++) {
            int cc = colw + j * 8;
            size_t o0 = (size_t)r0 * DIM + cc;
            size_t o1 = (size_t)r1 * DIM + cc;
            *reinterpret_cast<__half2*>(outh + o0) =
                __floats2half2_rn(acc[i][j][0] + bj[j][0], acc[i][j][1] + bj[j][1]);
            *reinterpret_cast<__half2*>(outh + o1) =
                __floats2half2_rn(acc[i][j][2] + bj[j][0], acc[i][j][3] + bj[j][1]);
        }
    }
}

// ===========================================================================
// GEMM2/3 (proven round-11 config): fp16 A/B, CTA 128x128, 256 thr, occ 2.
// MODE 1: per-batch B, fp16 addend added, fp16 out
// MODE 2: fp32 out + bias
// ===========================================================================
__device__ __forceinline__ void load_chunk(
    const __half* __restrict__ A, const __half* __restrict__ B,
    int m0, int n0, int c, uint32_t sA, uint32_t sB, int t)
{
    const int k0 = c * 64;
    const int ch = t & 7;
    const int rb = t >> 3;
#pragma unroll
    for (int it = 0; it < 4; it++) {
        int r = it * 32 + rb;
        cp16(sA + swz((uint32_t)(r * 128 + ch * 16)),
             A + (size_t)(m0 + r) * DIM + k0 + ch * 8);
    }
#pragma unroll
    for (int it = 0; it < 4; it++) {
        int r = it * 32 + rb;
        cp16(sB + swz((uint32_t)(r * 128 + ch * 16)),
             B + (size_t)(n0 + r) * DIM + k0 + ch * 8);
    }
}

template <int MODE>
__global__ __launch_bounds__(256, 2)
void mma_gemm(const __half* __restrict__ A, const __half* __restrict__ B,
              const float* __restrict__ bias0,
              const __half* __restrict__ addH,
              float* __restrict__ outF, __half* __restrict__ outH)
{
    extern __shared__ char smem[];
    const uint32_t sb = smem_u32(smem);
    const int t = threadIdx.x;
    const int w = t >> 5, l = t & 31;
    const int m0 = blockIdx.y * 128;
    const int n0 = blockIdx.x * 128;

    if (MODE == 1)
        B += (size_t)(m0 / SEQ) * DIM * DIM;

    uint32_t sA[STAGES], sB[STAGES];
#pragma unroll
    for (int s = 0; s < STAGES; s++) { sA[s] = sb + s * 32768u; sB[s] = sA[s] + 16384u; }

    load_chunk(A, B, m0, n0, 0, sA[0], sB[0], t); CP_COMMIT();
    load_chunk(A, B, m0, n0, 1, sA[1], sB[1], t); CP_COMMIT();

    const int wm = w & 1;
    const int wn = w >> 1;
    const uint32_t aBase = (uint32_t)((wm * 64 + (l & 15)) * 128 + (l >> 4) * 16);
    const uint32_t bBase = (uint32_t)((wn * 32 + ((l >> 4) * 8) + (l & 7)) * 128
                                      + ((l >> 3) & 1) * 16);

    float acc[4][4][4];
#pragma unroll
    for (int i = 0; i < 4; i++)
#pragma unroll
        for (int j = 0; j < 4; j++)
#pragma unroll
            for (int e = 0; e < 4; e++) acc[i][j][e] = 0.0f;

    for (int c = 0; c < 8; c++) {
        CP_WAIT1();
        __syncthreads();
        const int pf = c + 2;
        if (pf < 8)
            load_chunk(A, B, m0, n0, pf, sA[pf % 3], sB[pf % 3], t);
        CP_COMMIT();

        const uint32_t cA = sA[c % 3], cB = sB[c % 3];
#pragma unroll
        for (int s = 0; s < 4; s++) {
            uint32_t a[4][4], b[4][2];
#pragma unroll
            for (int i = 0; i < 4; i++) {
                uint32_t off = aBase + i * 2048 + s * 32;
                ldsm4(a[i], cA + (off ^ ((off >> 3) & 0x70)));
            }
#pragma unroll
            for (int jj = 0; jj < 2; jj++) {
                uint32_t off = bBase + jj * 2048 + s * 32;
                uint32_t r[4];
                ldsm4(r, cB + (off ^ ((off >> 3) & 0x70)));
                b[2 * jj][0] = r[0]; b[2 * jj][1] = r[1];
                b[2 * jj + 1][0] = r[2]; b[2 * jj + 1][1] = r[3];
            }
#pragma unroll
            for (int i = 0; i < 4; i++)
#pragma unroll
                for (int j = 0; j < 4; j++)
                    mma16816(acc[i][j], a[i], b[j]);
        }
    }

    const int colw = n0 + wn * 32 + (l & 3) * 2;
    float bj[4][2];
#pragma unroll
    for (int j = 0; j < 4; j++) {
        bj[j][0] = bias0[colw + j * 8];
        bj[j][1] = bias0[colw + j * 8 + 1];
    }

    const int mrow = m0 + wm * 64 + (l >> 2);
#pragma unroll
    for (int i = 0; i < 4; i++) {
        int r0 = mrow + i * 16, r1 = r0 + 8;
#pragma unroll
        for (int j = 0; j < 4; j++) {
            int cc = colw + j * 8;
            float v0 = acc[i][j][0] + bj[j][0];
            float v1 = acc[i][j][1] + bj[j][1];
            float v2 = acc[i][j][2] + bj[j][0];
            float v3 = acc[i][j][3] + bj[j][1];
            size_t o0 = (size_t)r0 * DIM + cc;
            size_t o1 = (size_t)r1 * DIM + cc;
            if (MODE == 1) {
                float2 a0 = __half22float2(*reinterpret_cast<const __half2*>(addH + o0));
                float2 a1 = __half22float2(*reinterpret_cast<const __half2*>(addH + o1));
                v0 += a0.x; v1 += a0.y; v2 += a1.x; v3 += a1.y;
                *reinterpret_cast<__half2*>(outH + o0) = __floats2half2_rn(v0, v1);
                *reinterpret_cast<__half2*>(outH + o1) = __floats2half2_rn(v2, v3);
            } else {
                *reinterpret_cast<float2*>(outF + o0) = make_float2(v0, v1);
                *reinterpret_cast<float2*>(outF + o1) = make_float2(v2, v3);
            }
        }
    }
}

// ---------------------------------------------------------------------------
// Transpose + convert one weight: th[zoff*D*D + n*D + k] = fp16(w[k][n])
// ---------------------------------------------------------------------------
__global__ void wsplit_kernel(const float* __restrict__ w,
                              __half* __restrict__ th, int zoff)
{
    __shared__ float sm[32][33];
    const int n0 = blockIdx.x * 32, k0 = blockIdx.y * 32;
    sm[threadIdx.y][threadIdx.x] = w[(size_t)(k0 + threadIdx.y) * DIM + n0 + threadIdx.x];
    __syncthreads();
    float v = sm[threadIdx.x][threadIdx.y];
    size_t o = (size_t)zoff * DIM * DIM + (size_t)(n0 + threadIdx.y) * DIM + k0 + threadIdx.x;
    th[o] = __float2half_rn(v);
}

// out[b][n][k] = fp16(gq[b][k] * wp[k][n])
__global__ void wpsplit_kernel(const float* __restrict__ wp,
                               const float* __restrict__ gq,
                               __half* __restrict__ th)
{
    __shared__ float sm[32][33];
    const int b = blockIdx.z;
    const int n0 = blockIdx.x * 32, k0 = blockIdx.y * 32;
    sm[threadIdx.y][threadIdx.x] = wp[(size_t)(k0 + threadIdx.y) * DIM + n0 + threadIdx.x];
    __syncthreads();
    float v = sm[threadIdx.x][threadIdx.y] * gq[b * DIM + k0 + threadIdx.x];
    size_t o = (size_t)b * DIM * DIM + (size_t)(n0 + threadIdx.y) * DIM + k0 + threadIdx.x;
    th[o] = __float2half_rn(v);
}

// ---------------------------------------------------------------------------
// L2-normalize q and k (fp16 in place), warp-per-row (round-11 proven form).
// ---------------------------------------------------------------------------
__device__ __forceinline__ float ss_acc(uint4 v) {
    const __half2* h = reinterpret_cast<const __half2*>(&v);
    float s = 0.f;
#pragma unroll
    for (int i = 0; i < 4; i++) {
        float2 f = __half22float2(h[i]);
        s += f.x * f.x + f.y * f.y;
    }
    return s;
}
__device__ __forceinline__ uint4 scale4(uint4 v, float r) {
    __half2* h = reinterpret_cast<__half2*>(&v);
#pragma unroll
    for (int i = 0; i < 4; i++) {
        float2 f = __half22float2(h[i]);
        h[i] = __floats2half2_rn(f.x * r, f.y * r);
    }
    return v;
}

__global__ void l2norm_kernel(__half* __restrict__ q, __half* __restrict__ k)
{
    const int lane = threadIdx.x & 31;
    const int wid  = threadIdx.x >> 5;
    const int row  = blockIdx.x * 8 + wid;

    uint4* qp = reinterpret_cast<uint4*>(q + (size_t)row * DIM);
    uint4* kp = reinterpret_cast<uint4*>(k + (size_t)row * DIM);
    uint4 q0 = qp[2 * lane], q1 = qp[2 * lane + 1];
    uint4 k0 = kp[2 * lane], k1 = kp[2 * lane + 1];

    float sq = ss_acc(q0) + ss_acc(q1);
    float sk = ss_acc(k0) + ss_acc(k1);
#pragma unroll
    for (int o = 16; o > 0; o >>= 1) {
        sq += __shfl_xor_sync(0xFFFFFFFFu, sq, o);
        sk += __shfl_xor_sync(0xFFFFFFFFu, sk, o);
    }
    const float rq = rsqrtf(fmaxf(sq, 1e-12f));
    const float rk = rsqrtf(fmaxf(sk, 1e-12f));

    qp[2 * lane]     = scale4(q0, rq);
    qp[2 * lane + 1] = scale4(q1, rq);
    kp[2 * lane]     = scale4(k0, rk);
    kp[2 * lane + 1] = scale4(k1, rk);
}

__global__ void zero_gq_kernel(float* __restrict__ gq, int base)
{
    int i = base + blockIdx.x * blockDim.x + threadIdx.x;
    if (i < BATCH * DIM) gq[i] = 0.0f;
}

// gq[b,d] = sum_n qn[b,n,d]  (qn normalized fp16)
__global__ void batch_sum_kernel(const __half* __restrict__ qn, float* __restrict__ gq)
{
    const int d4 = threadIdx.x;
    const int b  = blockIdx.y;
    const int n0 = blockIdx.z * 256;
    const __half2* base = reinterpret_cast<const __half2*>(
        qn + ((size_t)b * SEQ + n0) * DIM) + 2 * d4;
    float s0 = 0.f, s1 = 0.f, s2 = 0.f, s3 = 0.f;
#pragma unroll 8
    for (int i = 0; i < 256; i++) {
        float2 v0 = __half22float2(base[(size_t)i * (DIM / 2)]);
        float2 v1 = __half22float2(base[(size_t)i * (DIM / 2) + 1]);
        s0 += v0.x; s1 += v0.y; s2 += v1.x; s3 += v1.y;
    }
    float* g = gq + b * DIM + d4 * 4;
    atomicAdd(g + 0, s0);
    atomicAdd(g + 1, s1);
    atomicAdd(g + 2, s2);
    atomicAdd(g + 3, s3);
}

// ---------------------------------------------------------------------------
extern "C" void kernel_launch(void* const* d_in, const int* in_sizes, int n_in,
                              void* d_out, int out_size)
{
    const float* x  = (const float*)d_in[0];
    const float* wq = (const float*)d_in[1];
    const float* bq = (const float*)d_in[2];
    const float* wk = (const float*)d_in[3];
    const float* bk = (const float*)d_in[4];
    const float* wp = (const float*)d_in[5];
    const float* bp = (const float*)d_in[6];
    const float* wf = (const float*)d_in[7];
    const float* bf = (const float*)d_in[8];
    // d_in[9] = w_g: softmax over size-1 axis == 1 -> unused
    float* out = (float*)d_out;

    __half *uh, *qh, *kh, *wT, *wpT;
    float *gq;
    cudaGetSymbolAddress((void**)&uh,  g_uh);
    cudaGetSymbolAddress((void**)&qh,  g_qh);
    cudaGetSymbolAddress((void**)&kh,  g_kh);
    cudaGetSymbolAddress((void**)&wT,  g_wT);
    cudaGetSymbolAddress((void**)&wpT, g_wpT);
    cudaGetSymbolAddress((void**)&gq,  g_gq);

    cudaFuncSetAttribute(mma_gemm1,  cudaFuncAttributeMaxDynamicSharedMemorySize, GEMM_SMEM);
    cudaFuncSetAttribute(mma_gemm<1>, cudaFuncAttributeMaxDynamicSharedMemorySize, GEMM_SMEM);
    cudaFuncSetAttribute(mma_gemm<2>, cudaFuncAttributeMaxDynamicSharedMemorySize, GEMM_SMEM);

    const int MT = M_TOTAL / 128;   // 256 row tiles

    // launches 0-4 (prep; GEMM1 is launch index 5 for ncu -s 5 -c 1)
    wsplit_kernel<<<dim3(16, 16), dim3(32, 32)>>>(wq, wT, 0);
    wsplit_kernel<<<dim3(16, 16), dim3(32, 32)>>>(wk, wT, 1);
    wsplit_kernel<<<dim3(16, 16), dim3(32, 32)>>>(wf, wT, 2);
    zero_gq_kernel<<<8, 256>>>(gq, 0);
    zero_gq_kernel<<<8, 256>>>(gq, 2048);

    // launch 5: GEMM1 with in-kernel fp32->fp16 A conversion (cvt_x deleted)
    mma_gemm1<<<dim3(8, MT), 256, GEMM_SMEM>>>(x, wT, bq, bk, qh, kh);

    // normalize (fp16 in place, warp per row)
    l2norm_kernel<<<M_TOTAL / 8, 256>>>(qh, kh);
    // gq = per-batch sum of qn
    batch_sum_kernel<<<dim3(1, BATCH, SEQ / 256), 128>>>(qh, gq);
    // per-batch scaled wp (transposed, fp16)
    wpsplit_kernel<<<dim3(16, 16, BATCH), dim3(32, 32)>>>(wp, gq, wpT);

    // u = kn @ (diag(gq_b) wp) + bp + qn  -> fp16
    mma_gemm<1><<<dim3(4, MT), 256, GEMM_SMEM>>>(kh, wpT, bp, qh, nullptr, uh);
    // out = u @ wf + bf
    mma_gemm<2><<<dim3(4, MT), 256, GEMM_SMEM>>>(uh, wT + 2u * DIM * DIM, bf,
                                                 nullptr, out, nullptr);
}